// round 1
// baseline (speedup 1.0000x reference)
#include <cuda_runtime.h>
#include <cuda_bf16.h>

// Shapes
#define BATCH 8
#define CH    1024      // tokens == channels
#define PIX   1024      // 32*32
#define NH    16
#define HD    64
#define KTOT  9216      // CH * 9

// ---------------- device scratch (no runtime allocation allowed) ----------------
__device__ float g_q [BATCH * CH * PIX];                 // conv(q) output [B, C, P]
__device__ float g_k [BATCH * CH * PIX];
__device__ float g_v [BATCH * CH * PIX];
__device__ float g_s [(size_t)BATCH * NH * CH * CH];     // attention scores / probs [B*h, 1024, 1024]
__device__ float g_ao[BATCH * CH * PIX];                 // attention output [B, C, h*d]

// =================================================================================
// Kernel 1: 3x3 SAME conv as implicit GEMM.
//   Y[b, o, p] = bias[o] + sum_{c, kh, kw} W[o, c, kh, kw] * X[b, c, py+kh-1, px+kw-1]
// GEMM view per batch: M=CH (o), N=PIX (p), K=KTOT (c*9 + t), A=W row-major [O, K],
// B formed on the fly from shifted X.
// Tiling: BM=BN=128, BK=8, 256 threads, 8x8 per thread.
// =================================================================================
__global__ __launch_bounds__(256, 2)
void conv_gemm(const float* __restrict__ X, const float* __restrict__ W,
               const float* __restrict__ bias, float* __restrict__ Y)
{
    __shared__ float As[8][128];   // [k][m]  (transposed W tile)
    __shared__ float Bs[8][128];   // [k][n]

    const int b  = blockIdx.z;
    const int m0 = blockIdx.y * 128;
    const int n0 = blockIdx.x * 128;
    const int tid = threadIdx.x;
    const int tx = tid & 15;       // n direction (8 per thread)
    const int ty = tid >> 4;       // m direction (8 per thread)

    const float* Xb = X + (size_t)b * CH * PIX;

    // loader indices
    const int lm   = tid >> 1;           // 0..127
    const int lk4  = (tid & 1) * 4;      // 0 or 4
    const int lkr  = tid >> 5;           // 0..7   (B k-row)
    const int ln4  = (tid & 31) * 4;     // 0..124 (B n)

    float acc[8][8];
    #pragma unroll
    for (int i = 0; i < 8; i++)
        #pragma unroll
        for (int j = 0; j < 8; j++) acc[i][j] = 0.f;

    for (int k0 = 0; k0 < KTOT; k0 += 8) {
        // ---- load A (W) tile, transposed into smem ----
        float4 wa = *(const float4*)(W + (size_t)(m0 + lm) * KTOT + k0 + lk4);
        As[lk4 + 0][lm] = wa.x;
        As[lk4 + 1][lm] = wa.y;
        As[lk4 + 2][lm] = wa.z;
        As[lk4 + 3][lm] = wa.w;

        // ---- load B (shifted X) tile ----
        {
            const int k  = k0 + lkr;
            const int c  = k / 9;
            const int t  = k - c * 9;
            const int dy = t / 3 - 1;
            const int dx = t - (t / 3) * 3 - 1;
            const float* Xc = Xb + (size_t)c * PIX;
            float bv[4];
            #pragma unroll
            for (int j = 0; j < 4; j++) {
                int p  = n0 + ln4 + j;
                int py = p >> 5, px = p & 31;
                int sy = py + dy, sx = px + dx;
                bv[j] = (sy >= 0 && sy < 32 && sx >= 0 && sx < 32)
                            ? Xc[(sy << 5) + sx] : 0.f;
            }
            *(float4*)&Bs[lkr][ln4] = make_float4(bv[0], bv[1], bv[2], bv[3]);
        }
        __syncthreads();

        // ---- compute ----
        #pragma unroll
        for (int kk = 0; kk < 8; kk++) {
            float a[8], bb[8];
            *(float4*)(a)      = *(const float4*)&As[kk][ty * 8];
            *(float4*)(a + 4)  = *(const float4*)&As[kk][ty * 8 + 4];
            *(float4*)(bb)     = *(const float4*)&Bs[kk][tx * 8];
            *(float4*)(bb + 4) = *(const float4*)&Bs[kk][tx * 8 + 4];
            #pragma unroll
            for (int i = 0; i < 8; i++)
                #pragma unroll
                for (int j = 0; j < 8; j++)
                    acc[i][j] += a[i] * bb[j];
        }
        __syncthreads();
    }

    // ---- epilogue: + bias, write ----
    #pragma unroll
    for (int i = 0; i < 8; i++) {
        const int m = m0 + ty * 8 + i;
        const float bi = bias[m];
        float* yp = Y + (size_t)b * CH * PIX + (size_t)m * PIX + n0 + tx * 8;
        *(float4*)(yp)     = make_float4(acc[i][0] + bi, acc[i][1] + bi,
                                         acc[i][2] + bi, acc[i][3] + bi);
        *(float4*)(yp + 4) = make_float4(acc[i][4] + bi, acc[i][5] + bi,
                                         acc[i][6] + bi, acc[i][7] + bi);
    }
}

// =================================================================================
// Kernel 2: S = (Qh @ Kh^T) * scale, masked.  NT GEMM, K=64, per (b,h).
//   Qh row base: g_q + b*C*P + h*64, row stride 1024.
// grid: (8 s-tiles, 8 t-tiles, 128 bh), BM=BN=128, BK=8, 8x8/thread.
// =================================================================================
__global__ __launch_bounds__(256, 2)
void qk_gemm(const float* __restrict__ Q, const float* __restrict__ K,
             const int* __restrict__ mask, float* __restrict__ S)
{
    __shared__ float As[8][128];
    __shared__ float Bs[8][128];

    const int bh = blockIdx.z;
    const int b  = bh >> 4;
    const int h  = bh & 15;
    const int m0 = blockIdx.y * 128;
    const int n0 = blockIdx.x * 128;
    const int tid = threadIdx.x;
    const int tx = tid & 15, ty = tid >> 4;

    const float* Qb = Q + (size_t)b * CH * PIX + h * HD;
    const float* Kb = K + (size_t)b * CH * PIX + h * HD;

    const int lm  = tid >> 1;
    const int lk4 = (tid & 1) * 4;

    float acc[8][8];
    #pragma unroll
    for (int i = 0; i < 8; i++)
        #pragma unroll
        for (int j = 0; j < 8; j++) acc[i][j] = 0.f;

    for (int k0 = 0; k0 < HD; k0 += 8) {
        float4 qa = *(const float4*)(Qb + (size_t)(m0 + lm) * PIX + k0 + lk4);
        As[lk4 + 0][lm] = qa.x; As[lk4 + 1][lm] = qa.y;
        As[lk4 + 2][lm] = qa.z; As[lk4 + 3][lm] = qa.w;
        float4 ka = *(const float4*)(Kb + (size_t)(n0 + lm) * PIX + k0 + lk4);
        Bs[lk4 + 0][lm] = ka.x; Bs[lk4 + 1][lm] = ka.y;
        Bs[lk4 + 2][lm] = ka.z; Bs[lk4 + 3][lm] = ka.w;
        __syncthreads();
        #pragma unroll
        for (int kk = 0; kk < 8; kk++) {
            float a[8], bb[8];
            *(float4*)(a)      = *(const float4*)&As[kk][ty * 8];
            *(float4*)(a + 4)  = *(const float4*)&As[kk][ty * 8 + 4];
            *(float4*)(bb)     = *(const float4*)&Bs[kk][tx * 8];
            *(float4*)(bb + 4) = *(const float4*)&Bs[kk][tx * 8 + 4];
            #pragma unroll
            for (int i = 0; i < 8; i++)
                #pragma unroll
                for (int j = 0; j < 8; j++)
                    acc[i][j] += a[i] * bb[j];
        }
        __syncthreads();
    }

    const float scale = 0.125f;  // 1/sqrt(64)
    const size_t sbase = (size_t)bh * CH * CH;
    const int* mb = mask + (size_t)b * CH * CH;
    #pragma unroll
    for (int i = 0; i < 8; i++) {
        const int t = m0 + ty * 8 + i;
        const int4* mp = (const int4*)(mb + (size_t)t * CH + n0 + tx * 8);
        int4 m1 = mp[0], m2 = mp[1];
        float v[8];
        #pragma unroll
        for (int j = 0; j < 8; j++) v[j] = acc[i][j] * scale;
        if (m1.x == 0) v[0] = -1e9f;  if (m1.y == 0) v[1] = -1e9f;
        if (m1.z == 0) v[2] = -1e9f;  if (m1.w == 0) v[3] = -1e9f;
        if (m2.x == 0) v[4] = -1e9f;  if (m2.y == 0) v[5] = -1e9f;
        if (m2.z == 0) v[6] = -1e9f;  if (m2.w == 0) v[7] = -1e9f;
        float* sp = S + sbase + (size_t)t * CH + n0 + tx * 8;
        *(float4*)(sp)     = make_float4(v[0], v[1], v[2], v[3]);
        *(float4*)(sp + 4) = make_float4(v[4], v[5], v[6], v[7]);
    }
}

// =================================================================================
// Kernel 3: row softmax over 1024 elems. One warp per row, 8 warps/block.
// =================================================================================
__global__ __launch_bounds__(256)
void softmax_k(float* __restrict__ S)
{
    const int row  = blockIdx.x * 8 + (threadIdx.x >> 5);
    const int lane = threadIdx.x & 31;
    float* r = S + (size_t)row * CH;

    float4 v[8];
    float mx = -3.4e38f;
    #pragma unroll
    for (int i = 0; i < 8; i++) {
        v[i] = *(const float4*)(r + i * 128 + lane * 4);
        mx = fmaxf(mx, fmaxf(fmaxf(v[i].x, v[i].y), fmaxf(v[i].z, v[i].w)));
    }
    #pragma unroll
    for (int o = 16; o > 0; o >>= 1)
        mx = fmaxf(mx, __shfl_xor_sync(0xffffffffu, mx, o));

    float sum = 0.f;
    #pragma unroll
    for (int i = 0; i < 8; i++) {
        v[i].x = expf(v[i].x - mx);
        v[i].y = expf(v[i].y - mx);
        v[i].z = expf(v[i].z - mx);
        v[i].w = expf(v[i].w - mx);
        sum += (v[i].x + v[i].y) + (v[i].z + v[i].w);
    }
    #pragma unroll
    for (int o = 16; o > 0; o >>= 1)
        sum += __shfl_xor_sync(0xffffffffu, sum, o);

    const float inv = 1.f / sum;
    #pragma unroll
    for (int i = 0; i < 8; i++) {
        v[i].x *= inv; v[i].y *= inv; v[i].z *= inv; v[i].w *= inv;
        *(float4*)(r + i * 128 + lane * 4) = v[i];
    }
}

// =================================================================================
// Kernel 4: O = P @ Vh  (NN GEMM: M=1024 t, N=64 d, K=1024 s) per (b,h).
// grid: (8 t-tiles, 128 bh). BM=128, BN=64, BK=16, 256 threads, 8x4/thread.
// Writes O straight into [B, t, h*64+d] layout.
// =================================================================================
__global__ __launch_bounds__(256, 2)
void pv_gemm(const float* __restrict__ S, const float* __restrict__ V,
             float* __restrict__ O)
{
    __shared__ float As[16][128];  // [k(s)][m(t)]
    __shared__ float Bs[16][64];   // [k(s)][n(d)]

    const int bh = blockIdx.y;
    const int b  = bh >> 4;
    const int h  = bh & 15;
    const int m0 = blockIdx.x * 128;
    const int tid = threadIdx.x;
    const int tx = tid & 15;  // n: 4 per thread
    const int ty = tid >> 4;  // m: 8 per thread

    const float* Pm = S + ((size_t)bh << 20);            // [1024,1024]
    const float* Vb = V + (size_t)b * CH * PIX + h * HD; // rows s, stride 1024

    const int lm  = tid >> 1;          // A: 0..127
    const int lk8 = (tid & 1) * 8;     // A: 0 or 8
    const int lkr = tid >> 4;          // B: 0..15
    const int ln4 = (tid & 15) * 4;    // B: 0..60

    float acc[8][4];
    #pragma unroll
    for (int i = 0; i < 8; i++)
        #pragma unroll
        for (int j = 0; j < 4; j++) acc[i][j] = 0.f;

    for (int k0 = 0; k0 < CH; k0 += 16) {
        float4 p1 = *(const float4*)(Pm + (size_t)(m0 + lm) * CH + k0 + lk8);
        float4 p2 = *(const float4*)(Pm + (size_t)(m0 + lm) * CH + k0 + lk8 + 4);
        As[lk8 + 0][lm] = p1.x; As[lk8 + 1][lm] = p1.y;
        As[lk8 + 2][lm] = p1.z; As[lk8 + 3][lm] = p1.w;
        As[lk8 + 4][lm] = p2.x; As[lk8 + 5][lm] = p2.y;
        As[lk8 + 6][lm] = p2.z; As[lk8 + 7][lm] = p2.w;
        *(float4*)&Bs[lkr][ln4] =
            *(const float4*)(Vb + (size_t)(k0 + lkr) * PIX + ln4);
        __syncthreads();
        #pragma unroll
        for (int kk = 0; kk < 16; kk++) {
            float a[8];
            *(float4*)(a)     = *(const float4*)&As[kk][ty * 8];
            *(float4*)(a + 4) = *(const float4*)&As[kk][ty * 8 + 4];
            float4 bb = *(const float4*)&Bs[kk][tx * 4];
            #pragma unroll
            for (int i = 0; i < 8; i++) {
                acc[i][0] += a[i] * bb.x;
                acc[i][1] += a[i] * bb.y;
                acc[i][2] += a[i] * bb.z;
                acc[i][3] += a[i] * bb.w;
            }
        }
        __syncthreads();
    }

    #pragma unroll
    for (int i = 0; i < 8; i++) {
        const int t = m0 + ty * 8 + i;
        float* op = O + (size_t)b * CH * PIX + (size_t)t * PIX + h * HD + tx * 4;
        *(float4*)op = make_float4(acc[i][0], acc[i][1], acc[i][2], acc[i][3]);
    }
}

// =================================================================================
// Kernel 5: out = AO @ Wo^T + bo.  NT GEMM M=8192, N=1024, K=1024.
// grid: (8 n-tiles, 64 m-tiles). Same skeleton as qk_gemm.
// =================================================================================
__global__ __launch_bounds__(256, 2)
void proj_gemm(const float* __restrict__ A, const float* __restrict__ Wo,
               const float* __restrict__ bo, float* __restrict__ Out)
{
    __shared__ float As[8][128];
    __shared__ float Bs[8][128];

    const int m0 = blockIdx.y * 128;
    const int n0 = blockIdx.x * 128;
    const int tid = threadIdx.x;
    const int tx = tid & 15, ty = tid >> 4;

    const int lm  = tid >> 1;
    const int lk4 = (tid & 1) * 4;

    float acc[8][8];
    #pragma unroll
    for (int i = 0; i < 8; i++)
        #pragma unroll
        for (int j = 0; j < 8; j++) acc[i][j] = 0.f;

    for (int k0 = 0; k0 < CH; k0 += 8) {
        float4 aa = *(const float4*)(A + (size_t)(m0 + lm) * CH + k0 + lk4);
        As[lk4 + 0][lm] = aa.x; As[lk4 + 1][lm] = aa.y;
        As[lk4 + 2][lm] = aa.z; As[lk4 + 3][lm] = aa.w;
        float4 wb = *(const float4*)(Wo + (size_t)(n0 + lm) * CH + k0 + lk4);
        Bs[lk4 + 0][lm] = wb.x; Bs[lk4 + 1][lm] = wb.y;
        Bs[lk4 + 2][lm] = wb.z; Bs[lk4 + 3][lm] = wb.w;
        __syncthreads();
        #pragma unroll
        for (int kk = 0; kk < 8; kk++) {
            float a[8], bb[8];
            *(float4*)(a)      = *(const float4*)&As[kk][ty * 8];
            *(float4*)(a + 4)  = *(const float4*)&As[kk][ty * 8 + 4];
            *(float4*)(bb)     = *(const float4*)&Bs[kk][tx * 8];
            *(float4*)(bb + 4) = *(const float4*)&Bs[kk][tx * 8 + 4];
            #pragma unroll
            for (int i = 0; i < 8; i++)
                #pragma unroll
                for (int j = 0; j < 8; j++)
                    acc[i][j] += a[i] * bb[j];
        }
        __syncthreads();
    }

    #pragma unroll
    for (int i = 0; i < 8; i++) {
        const int m = m0 + ty * 8 + i;
        float* op = Out + (size_t)m * CH + n0 + tx * 8;
        const float* bp = bo + n0 + tx * 8;
        *(float4*)(op)     = make_float4(acc[i][0] + bp[0], acc[i][1] + bp[1],
                                         acc[i][2] + bp[2], acc[i][3] + bp[3]);
        *(float4*)(op + 4) = make_float4(acc[i][4] + bp[4], acc[i][5] + bp[5],
                                         acc[i][6] + bp[6], acc[i][7] + bp[7]);
    }
}

// =================================================================================
// Launch
// =================================================================================
extern "C" void kernel_launch(void* const* d_in, const int* in_sizes, int n_in,
                              void* d_out, int out_size)
{
    const float* q    = (const float*)d_in[0];
    const float* k    = (const float*)d_in[1];
    const float* v    = (const float*)d_in[2];
    const float* Wq   = (const float*)d_in[3];
    const float* bq   = (const float*)d_in[4];
    const float* Wk   = (const float*)d_in[5];
    const float* bk   = (const float*)d_in[6];
    const float* Wv   = (const float*)d_in[7];
    const float* bv   = (const float*)d_in[8];
    const float* Wo   = (const float*)d_in[9];
    const float* bo   = (const float*)d_in[10];
    const int*   mask = (const int*)  d_in[11];

    float *pq, *pk, *pv_, *ps, *pao;
    cudaGetSymbolAddress((void**)&pq,  g_q);
    cudaGetSymbolAddress((void**)&pk,  g_k);
    cudaGetSymbolAddress((void**)&pv_, g_v);
    cudaGetSymbolAddress((void**)&ps,  g_s);
    cudaGetSymbolAddress((void**)&pao, g_ao);

    dim3 cgrid(PIX / 128, CH / 128, BATCH);   // (8, 8, 8)
    conv_gemm<<<cgrid, 256>>>(q, Wq, bq, pq);
    conv_gemm<<<cgrid, 256>>>(k, Wk, bk, pk);
    conv_gemm<<<cgrid, 256>>>(v, Wv, bv, pv_);

    qk_gemm<<<dim3(8, 8, BATCH * NH), 256>>>(pq, pk, mask, ps);

    softmax_k<<<(BATCH * NH * CH) / 8, 256>>>(ps);

    pv_gemm<<<dim3(8, BATCH * NH), 256>>>(ps, pv_, pao);

    proj_gemm<<<dim3(8, 64), 256>>>(pao, Wo, bo, (float*)d_out);
}

// round 3
// speedup vs baseline: 1.7422x; 1.7422x over previous
#include <cuda_runtime.h>
#include <cuda_bf16.h>
#include <cstdint>

// Shapes
#define BATCH 8
#define CH    1024
#define PIX   1024
#define NH    16
#define HD    64
#define KT    9216          // tap-major K for conv: k = t*1024 + c

// ---------------- device scratch ----------------
__device__ float g_q [BATCH * CH * PIX];
__device__ float g_k [BATCH * CH * PIX];
__device__ float g_v [BATCH * CH * PIX];
__device__ float g_s [(size_t)BATCH * NH * CH * CH];
__device__ float g_ao[BATCH * CH * PIX];
__device__ float g_zero[8192];                        // zero-initialized
// bf16 (as ushort) split buffers
__device__ unsigned short g_wh[(size_t)CH * KT];      // also reused for Wo split
__device__ unsigned short g_wl[(size_t)CH * KT];
__device__ unsigned short g_bh[(size_t)BATCH * PIX * KT];  // also reused for AO split
__device__ unsigned short g_bl[(size_t)BATCH * PIX * KT];

// ---------------- PTX helpers (sm_80-class only: works at compute_103 target) ---
__device__ __forceinline__ uint32_t smem_u32(const void* p) {
    uint32_t a;
    asm("{ .reg .u64 t; cvta.to.shared.u64 t, %1; cvt.u32.u64 %0, t; }" : "=r"(a) : "l"(p));
    return a;
}
__device__ __forceinline__ void cp_async16(uint32_t dst, const void* src) {
    asm volatile("cp.async.cg.shared.global [%0], [%1], 16;" :: "r"(dst), "l"(src) : "memory");
}
__device__ __forceinline__ void cp_commit() {
    asm volatile("cp.async.commit_group;" ::: "memory");
}
__device__ __forceinline__ void ldsm4(uint32_t* r, uint32_t addr) {
    asm volatile("ldmatrix.sync.aligned.m8n8.x4.shared.b16 {%0,%1,%2,%3}, [%4];"
                 : "=r"(r[0]), "=r"(r[1]), "=r"(r[2]), "=r"(r[3]) : "r"(addr));
}
__device__ __forceinline__ void mma16816(float* c, const uint32_t* a, const uint32_t* b) {
    asm volatile(
        "mma.sync.aligned.m16n8k16.row.col.f32.bf16.bf16.f32 "
        "{%0,%1,%2,%3}, {%4,%5,%6,%7}, {%8,%9}, {%0,%1,%2,%3};"
        : "+f"(c[0]), "+f"(c[1]), "+f"(c[2]), "+f"(c[3])
        : "r"(a[0]), "r"(a[1]), "r"(a[2]), "r"(a[3]), "r"(b[0]), "r"(b[1]));
}

// =================================================================================
// prep_w: W [O=1024, C*9] fp32 (k = c*9+t) -> Wh/Wl bf16 tap-major (k = t*1024+c)
// =================================================================================
__global__ __launch_bounds__(256)
void prep_w(const float* __restrict__ W, unsigned short* __restrict__ Wh,
            unsigned short* __restrict__ Wl)
{
    const int o = blockIdx.x;
    const int c = blockIdx.y * 256 + threadIdx.x;
    const float* src = W + (size_t)o * KT + c * 9;
    float v[9];
    #pragma unroll
    for (int t = 0; t < 9; t++) v[t] = src[t];
    #pragma unroll
    for (int t = 0; t < 9; t++) {
        size_t k = (size_t)o * KT + t * 1024 + c;
        __nv_bfloat16 hi = __float2bfloat16_rn(v[t]);
        __nv_bfloat16 lo = __float2bfloat16_rn(v[t] - __bfloat162float(hi));
        Wh[k] = __bfloat16_as_ushort(hi);
        Wl[k] = __bfloat16_as_ushort(lo);
    }
}

// =================================================================================
// im2col: X [B, C, 32, 32] fp32 -> Bcol_hi/lo [B, P=1024, KT] bf16 tap-major.
// =================================================================================
__global__ __launch_bounds__(256)
void im2col_k(const float* __restrict__ X, unsigned short* __restrict__ Bh,
              unsigned short* __restrict__ Bl)
{
    __shared__ float xs[32][261];

    const int bt = blockIdx.z;
    const int b  = bt / 9;
    const int t  = bt - b * 9;
    const int dy = t / 3 - 1;
    const int dx = t - (t / 3) * 3 - 1;
    const int c0 = blockIdx.y * 32;
    const int p0 = blockIdx.x * 256;
    const int tid = threadIdx.x;

    const float* Xb = X + (size_t)b * CH * PIX;
    const int s0 = p0 + dy * 32 - 1;

    for (int idx = tid; idx < 32 * 258; idx += 256) {
        int c = idx / 258;
        int jj = idx - c * 258;
        int s = s0 + jj;
        xs[c][jj] = (s >= 0 && s < PIX) ? Xb[(size_t)(c0 + c) * PIX + s] : 0.f;
    }
    __syncthreads();

    const int w = tid >> 5;
    const int lane = tid & 31;
    #pragma unroll 4
    for (int it = 0; it < 32; it++) {
        int p = p0 + w * 32 + it;
        int py = p >> 5, px = p & 31;
        int sy = py + dy, sx = px + dx;
        bool valid = ((unsigned)sy < 32u) && ((unsigned)sx < 32u);
        int j = (p - p0) + dx + 1;
        float x = valid ? xs[lane][j] : 0.f;
        __nv_bfloat16 hi = __float2bfloat16_rn(x);
        __nv_bfloat16 lo = __float2bfloat16_rn(x - __bfloat162float(hi));
        size_t off = ((size_t)b * PIX + p) * KT + t * 1024 + c0 + lane;
        Bh[off] = __bfloat16_as_ushort(hi);
        Bl[off] = __bfloat16_as_ushort(lo);
    }
}

// =================================================================================
// split_f32: fp32 -> bf16 hi/lo, vectorized x4
// =================================================================================
__global__ __launch_bounds__(256)
void split_f32(const float* __restrict__ src, unsigned short* __restrict__ dh,
               unsigned short* __restrict__ dl, int n4)
{
    int i = blockIdx.x * 256 + threadIdx.x;
    if (i >= n4) return;
    float4 v = ((const float4*)src)[i];
    float a[4] = {v.x, v.y, v.z, v.w};
    ushort4 h, l;
    unsigned short* hp = (unsigned short*)&h;
    unsigned short* lp = (unsigned short*)&l;
    #pragma unroll
    for (int j = 0; j < 4; j++) {
        __nv_bfloat16 hi = __float2bfloat16_rn(a[j]);
        __nv_bfloat16 lo = __float2bfloat16_rn(a[j] - __bfloat162float(hi));
        hp[j] = __bfloat16_as_ushort(hi);
        lp[j] = __bfloat16_as_ushort(lo);
    }
    ((ushort4*)dh)[i] = h;
    ((ushort4*)dl)[i] = l;
}

// =================================================================================
// gemm_mma: generic NT k-major bf16 hi/lo-split GEMM via mma.sync m16n8k16.
//   D[z, m, n] = sum_k (Ah+Al)[m,k] * (Bh+Bl)[z,n,k] + bm[m] + bn[n]   (ll dropped)
// A row m: Ah + m*K (elements). B row n: Bh + zB*z + n*K.
// BM=BN=128, BK=32, 256 threads (8 warps as 2x4), 3-stage cp.async pipeline.
// SMEM per stage: Ah|Al|Bh|Bl tiles, each 128 rows x 64B, XOR swizzle
//   phys_unit = u ^ ((row>>1)&3)   (16B units, 4 per row)
// =================================================================================
#define GSMEM (3 * 32768)

__global__ __launch_bounds__(256, 1)
void gemm_mma(const unsigned short* __restrict__ Ah_g, const unsigned short* __restrict__ Al_g,
              const unsigned short* __restrict__ Bh_g, const unsigned short* __restrict__ Bl_g,
              const float* __restrict__ bm, const float* __restrict__ bn,
              float* __restrict__ Y, int K, size_t zB, size_t zY)
{
    extern __shared__ char smem[];
    const uint32_t sb = smem_u32(smem);
    const int tid  = threadIdx.x;
    const int wid  = tid >> 5;
    const int lane = tid & 31;
    const int z  = blockIdx.z;
    const int m0 = blockIdx.y * 128;
    const int n0 = blockIdx.x * 128;
    const int wm = wid >> 2;        // 0..1 -> m offset wm*64
    const int wn = wid & 3;         // 0..3 -> n offset wn*32
    const int NS = K >> 5;          // stages of BK=32

    // ---------------- loader setup ----------------
    const int mat = tid >> 6;            // 0 Ah, 1 Al, 2 Bh, 3 Bl
    const int r0  = (tid & 63) * 2;      // tile rows r0, r0+1
    const size_t rowB = (size_t)K * 2;   // row stride bytes

    const unsigned short* gb;
    if      (mat == 0) gb = Ah_g + (size_t)(m0 + r0) * K;
    else if (mat == 1) gb = Al_g + (size_t)(m0 + r0) * K;
    else if (mat == 2) gb = Bh_g + zB * z + (size_t)(n0 + r0) * K;
    else               gb = Bl_g + zB * z + (size_t)(n0 + r0) * K;
    const char* gsrc = (const char*)gb;

    uint32_t swo[2][4];
    #pragma unroll
    for (int rr = 0; rr < 2; rr++)
        #pragma unroll
        for (int u = 0; u < 4; u++) {
            int r = r0 + rr;
            swo[rr][u] = (uint32_t)r * 64 + (uint32_t)((u ^ ((r >> 1) & 3)) * 16);
        }
    const uint32_t matOff = mat * 8192;

    // accumulators
    float acc[4][4][4];
    #pragma unroll
    for (int i = 0; i < 4; i++)
        #pragma unroll
        for (int j = 0; j < 4; j++)
            #pragma unroll
            for (int q = 0; q < 4; q++) acc[i][j][q] = 0.f;

    // ---------------- prologue: load stages 0, 1 ----------------
    #pragma unroll
    for (int s = 0; s < 2; s++) {
        const uint32_t dst = sb + s * 32768 + matOff;
        const char* sp = gsrc + (size_t)s * 64;
        #pragma unroll
        for (int rr = 0; rr < 2; rr++)
            #pragma unroll
            for (int u = 0; u < 4; u++)
                cp_async16(dst + swo[rr][u], sp + rr * rowB + u * 16);
        cp_commit();
    }

    // fragment row/unit bases (constant per thread)
    const int rA_base = wm * 64 + (lane & 15);
    const int uA_add  = lane >> 4;                        // 0/1
    const int rB_base = wn * 32 + (lane & 7) + ((lane >> 4) << 3);
    const int uB_add  = (lane >> 3) & 1;

    // ---------------- main loop ----------------
    for (int i = 0; i < NS; i++) {
        if (i + 1 < NS) asm volatile("cp.async.wait_group 1;" ::: "memory");
        else            asm volatile("cp.async.wait_group 0;" ::: "memory");
        __syncthreads();

        if (i + 2 < NS) {
            const uint32_t dst = sb + ((i + 2) % 3) * 32768 + matOff;
            const char* sp = gsrc + (size_t)(i + 2) * 64;
            #pragma unroll
            for (int rr = 0; rr < 2; rr++)
                #pragma unroll
                for (int u = 0; u < 4; u++)
                    cp_async16(dst + swo[rr][u], sp + rr * rowB + u * 16);
            cp_commit();
        }

        const uint32_t stA = sb + (i % 3) * 32768;        // Ah tile
        const uint32_t stB = stA + 16384;                 // Bh tile

        #pragma unroll
        for (int ks = 0; ks < 2; ks++) {
            uint32_t ah[4][4], al_[4][4];
            #pragma unroll
            for (int mt = 0; mt < 4; mt++) {
                const int r = rA_base + mt * 16;
                const int u = ks * 2 + uA_add;
                const uint32_t off = (uint32_t)r * 64 + (uint32_t)((u ^ ((r >> 1) & 3)) * 16);
                ldsm4(ah[mt],  stA + off);
                ldsm4(al_[mt], stA + 8192 + off);
            }
            uint32_t bh[4][2], bl[4][2];
            #pragma unroll
            for (int np = 0; np < 2; np++) {
                const int r = rB_base + np * 16;
                const int u = ks * 2 + uB_add;
                const uint32_t off = (uint32_t)r * 64 + (uint32_t)((u ^ ((r >> 1) & 3)) * 16);
                ldsm4(&bh[np * 2][0], stB + off);
                ldsm4(&bl[np * 2][0], stB + 8192 + off);
            }
            #pragma unroll
            for (int mt = 0; mt < 4; mt++)
                #pragma unroll
                for (int nt = 0; nt < 4; nt++) {
                    mma16816(acc[mt][nt], ah[mt],  bh[nt]);
                    mma16816(acc[mt][nt], ah[mt],  bl[nt]);
                    mma16816(acc[mt][nt], al_[mt], bh[nt]);
                }
        }
    }

    // ---------------- epilogue ----------------
    const int g  = lane >> 2;
    const int cq = (lane & 3) * 2;
    float* Yz = Y + zY * z;
    #pragma unroll
    for (int mt = 0; mt < 4; mt++) {
        const int m = m0 + wm * 64 + mt * 16 + g;
        const float bm0 = bm[m];
        const float bm1 = bm[m + 8];
        #pragma unroll
        for (int nt = 0; nt < 4; nt++) {
            const int n = n0 + wn * 32 + nt * 8 + cq;
            const float bn0 = bn[n];
            const float bn1 = bn[n + 1];
            float2 v0 = make_float2(acc[mt][nt][0] + bm0 + bn0,
                                    acc[mt][nt][1] + bm0 + bn1);
            float2 v1 = make_float2(acc[mt][nt][2] + bm1 + bn0,
                                    acc[mt][nt][3] + bm1 + bn1);
            *(float2*)(Yz + (size_t)m * 1024 + n)       = v0;
            *(float2*)(Yz + (size_t)(m + 8) * 1024 + n) = v1;
        }
    }
}

// =================================================================================
// qk_gemm (SIMT, unchanged)
// =================================================================================
__global__ __launch_bounds__(256, 2)
void qk_gemm(const float* __restrict__ Q, const float* __restrict__ K,
             const int* __restrict__ mask, float* __restrict__ S)
{
    __shared__ float As[8][128];
    __shared__ float Bs[8][128];

    const int bh = blockIdx.z;
    const int b  = bh >> 4;
    const int h  = bh & 15;
    const int m0 = blockIdx.y * 128;
    const int n0 = blockIdx.x * 128;
    const int tid = threadIdx.x;
    const int tx = tid & 15, ty = tid >> 4;

    const float* Qb = Q + (size_t)b * CH * PIX + h * HD;
    const float* Kb = K + (size_t)b * CH * PIX + h * HD;

    const int lm  = tid >> 1;
    const int lk4 = (tid & 1) * 4;

    float acc[8][8];
    #pragma unroll
    for (int i = 0; i < 8; i++)
        #pragma unroll
        for (int j = 0; j < 8; j++) acc[i][j] = 0.f;

    for (int k0 = 0; k0 < HD; k0 += 8) {
        float4 qa = *(const float4*)(Qb + (size_t)(m0 + lm) * PIX + k0 + lk4);
        As[lk4 + 0][lm] = qa.x; As[lk4 + 1][lm] = qa.y;
        As[lk4 + 2][lm] = qa.z; As[lk4 + 3][lm] = qa.w;
        float4 ka = *(const float4*)(Kb + (size_t)(n0 + lm) * PIX + k0 + lk4);
        Bs[lk4 + 0][lm] = ka.x; Bs[lk4 + 1][lm] = ka.y;
        Bs[lk4 + 2][lm] = ka.z; Bs[lk4 + 3][lm] = ka.w;
        __syncthreads();
        #pragma unroll
        for (int kk = 0; kk < 8; kk++) {
            float a[8], bb[8];
            *(float4*)(a)      = *(const float4*)&As[kk][ty * 8];
            *(float4*)(a + 4)  = *(const float4*)&As[kk][ty * 8 + 4];
            *(float4*)(bb)     = *(const float4*)&Bs[kk][tx * 8];
            *(float4*)(bb + 4) = *(const float4*)&Bs[kk][tx * 8 + 4];
            #pragma unroll
            for (int i = 0; i < 8; i++)
                #pragma unroll
                for (int j = 0; j < 8; j++)
                    acc[i][j] += a[i] * bb[j];
        }
        __syncthreads();
    }

    const float scale = 0.125f;
    const size_t sbase = (size_t)bh * CH * CH;
    const int* mb = mask + (size_t)b * CH * CH;
    #pragma unroll
    for (int i = 0; i < 8; i++) {
        const int t = m0 + ty * 8 + i;
        const int4* mp = (const int4*)(mb + (size_t)t * CH + n0 + tx * 8);
        int4 m1 = mp[0], m2 = mp[1];
        float v[8];
        #pragma unroll
        for (int j = 0; j < 8; j++) v[j] = acc[i][j] * scale;
        if (m1.x == 0) v[0] = -1e9f;  if (m1.y == 0) v[1] = -1e9f;
        if (m1.z == 0) v[2] = -1e9f;  if (m1.w == 0) v[3] = -1e9f;
        if (m2.x == 0) v[4] = -1e9f;  if (m2.y == 0) v[5] = -1e9f;
        if (m2.z == 0) v[6] = -1e9f;  if (m2.w == 0) v[7] = -1e9f;
        float* sp = S + sbase + (size_t)t * CH + n0 + tx * 8;
        *(float4*)(sp)     = make_float4(v[0], v[1], v[2], v[3]);
        *(float4*)(sp + 4) = make_float4(v[4], v[5], v[6], v[7]);
    }
}

// =================================================================================
// softmax (unchanged)
// =================================================================================
__global__ __launch_bounds__(256)
void softmax_k(float* __restrict__ S)
{
    const int row  = blockIdx.x * 8 + (threadIdx.x >> 5);
    const int lane = threadIdx.x & 31;
    float* r = S + (size_t)row * CH;

    float4 v[8];
    float mx = -3.4e38f;
    #pragma unroll
    for (int i = 0; i < 8; i++) {
        v[i] = *(const float4*)(r + i * 128 + lane * 4);
        mx = fmaxf(mx, fmaxf(fmaxf(v[i].x, v[i].y), fmaxf(v[i].z, v[i].w)));
    }
    #pragma unroll
    for (int o = 16; o > 0; o >>= 1)
        mx = fmaxf(mx, __shfl_xor_sync(0xffffffffu, mx, o));

    float sum = 0.f;
    #pragma unroll
    for (int i = 0; i < 8; i++) {
        v[i].x = expf(v[i].x - mx);
        v[i].y = expf(v[i].y - mx);
        v[i].z = expf(v[i].z - mx);
        v[i].w = expf(v[i].w - mx);
        sum += (v[i].x + v[i].y) + (v[i].z + v[i].w);
    }
    #pragma unroll
    for (int o = 16; o > 0; o >>= 1)
        sum += __shfl_xor_sync(0xffffffffu, sum, o);

    const float inv = 1.f / sum;
    #pragma unroll
    for (int i = 0; i < 8; i++) {
        v[i].x *= inv; v[i].y *= inv; v[i].z *= inv; v[i].w *= inv;
        *(float4*)(r + i * 128 + lane * 4) = v[i];
    }
}

// =================================================================================
// pv_gemm (SIMT, unchanged)
// =================================================================================
__global__ __launch_bounds__(256, 2)
void pv_gemm(const float* __restrict__ S, const float* __restrict__ V,
             float* __restrict__ O)
{
    __shared__ float As[16][128];
    __shared__ float Bs[16][64];

    const int bh = blockIdx.y;
    const int b  = bh >> 4;
    const int h  = bh & 15;
    const int m0 = blockIdx.x * 128;
    const int tid = threadIdx.x;
    const int tx = tid & 15;
    const int ty = tid >> 4;

    const float* Pm = S + ((size_t)bh << 20);
    const float* Vb = V + (size_t)b * CH * PIX + h * HD;

    const int lm  = tid >> 1;
    const int lk8 = (tid & 1) * 8;
    const int lkr = tid >> 4;
    const int ln4 = (tid & 15) * 4;

    float acc[8][4];
    #pragma unroll
    for (int i = 0; i < 8; i++)
        #pragma unroll
        for (int j = 0; j < 4; j++) acc[i][j] = 0.f;

    for (int k0 = 0; k0 < CH; k0 += 16) {
        float4 p1 = *(const float4*)(Pm + (size_t)(m0 + lm) * CH + k0 + lk8);
        float4 p2 = *(const float4*)(Pm + (size_t)(m0 + lm) * CH + k0 + lk8 + 4);
        As[lk8 + 0][lm] = p1.x; As[lk8 + 1][lm] = p1.y;
        As[lk8 + 2][lm] = p1.z; As[lk8 + 3][lm] = p1.w;
        As[lk8 + 4][lm] = p2.x; As[lk8 + 5][lm] = p2.y;
        As[lk8 + 6][lm] = p2.z; As[lk8 + 7][lm] = p2.w;
        *(float4*)&Bs[lkr][ln4] =
            *(const float4*)(Vb + (size_t)(k0 + lkr) * PIX + ln4);
        __syncthreads();
        #pragma unroll
        for (int kk = 0; kk < 16; kk++) {
            float a[8];
            *(float4*)(a)     = *(const float4*)&As[kk][ty * 8];
            *(float4*)(a + 4) = *(const float4*)&As[kk][ty * 8 + 4];
            float4 bb = *(const float4*)&Bs[kk][tx * 4];
            #pragma unroll
            for (int i = 0; i < 8; i++) {
                acc[i][0] += a[i] * bb.x;
                acc[i][1] += a[i] * bb.y;
                acc[i][2] += a[i] * bb.z;
                acc[i][3] += a[i] * bb.w;
            }
        }
        __syncthreads();
    }

    #pragma unroll
    for (int i = 0; i < 8; i++) {
        const int t = m0 + ty * 8 + i;
        float* op = O + (size_t)b * CH * PIX + (size_t)t * PIX + h * HD + tx * 4;
        *(float4*)op = make_float4(acc[i][0], acc[i][1], acc[i][2], acc[i][3]);
    }
}

// =================================================================================
// Launch
// =================================================================================
extern "C" void kernel_launch(void* const* d_in, const int* in_sizes, int n_in,
                              void* d_out, int out_size)
{
    const float* q    = (const float*)d_in[0];
    const float* k    = (const float*)d_in[1];
    const float* v    = (const float*)d_in[2];
    const float* Wq   = (const float*)d_in[3];
    const float* bq   = (const float*)d_in[4];
    const float* Wk   = (const float*)d_in[5];
    const float* bk   = (const float*)d_in[6];
    const float* Wv   = (const float*)d_in[7];
    const float* bv   = (const float*)d_in[8];
    const float* Wo   = (const float*)d_in[9];
    const float* bo   = (const float*)d_in[10];
    const int*   mask = (const int*)  d_in[11];

    float *pq, *pk, *pv_, *ps, *pao, *pz;
    unsigned short *pwh, *pwl, *pbh, *pbl;
    cudaGetSymbolAddress((void**)&pq,  g_q);
    cudaGetSymbolAddress((void**)&pk,  g_k);
    cudaGetSymbolAddress((void**)&pv_, g_v);
    cudaGetSymbolAddress((void**)&ps,  g_s);
    cudaGetSymbolAddress((void**)&pao, g_ao);
    cudaGetSymbolAddress((void**)&pz,  g_zero);
    cudaGetSymbolAddress((void**)&pwh, g_wh);
    cudaGetSymbolAddress((void**)&pwl, g_wl);
    cudaGetSymbolAddress((void**)&pbh, g_bh);
    cudaGetSymbolAddress((void**)&pbl, g_bl);

    static bool attr_set = false;
    if (!attr_set) {
        cudaFuncSetAttribute(gemm_mma, cudaFuncAttributeMaxDynamicSharedMemorySize, GSMEM);
        attr_set = true;
    }

    // ---- convs: Y = conv3x3(X, W) + b via im2col + split-bf16 HMMA GEMM ----
    const float* Xs[3] = {q, k, v};
    const float* Ws[3] = {Wq, Wk, Wv};
    const float* bs[3] = {bq, bk, bv};
    float*       Ys[3] = {pq, pk, pv_};
    for (int i = 0; i < 3; i++) {
        prep_w  <<<dim3(1024, 4), 256>>>(Ws[i], pwh, pwl);
        im2col_k<<<dim3(4, 32, 72), 256>>>(Xs[i], pbh, pbl);
        gemm_mma<<<dim3(8, 8, BATCH), 256, GSMEM>>>(
            pwh, pwl, pbh, pbl, bs[i], pz, Ys[i],
            KT, (size_t)PIX * KT, (size_t)CH * PIX);
    }

    // ---- attention ----
    qk_gemm<<<dim3(8, 8, BATCH * NH), 256>>>(pq, pk, mask, ps);
    softmax_k<<<(BATCH * NH * CH) / 8, 256>>>(ps);
    pv_gemm<<<dim3(8, BATCH * NH), 256>>>(ps, pv_, pao);

    // ---- output projection: out = AO @ Wo^T + bo via split-bf16 HMMA GEMM ----
    split_f32<<<(BATCH * CH * PIX / 4 + 255) / 256, 256>>>(pao, pbh, pbl, BATCH * CH * PIX / 4);
    split_f32<<<(CH * CH / 4 + 255) / 256, 256>>>(Wo, pwh, pwl, CH * CH / 4);
    gemm_mma<<<dim3(8, 64, 1), 256, GSMEM>>>(
        pbh, pbl, pwh, pwl, pz, bo, (float*)d_out,
        CH, 0, 0);
}